// round 4
// baseline (speedup 1.0000x reference)
#include <cuda_runtime.h>
#include <cuda_bf16.h>

#define B_SZ 16384
#define FDIM 2048
#define HID  256
#define NN   9

// ---------------- scratch (static device globals; no allocations) ----------
__device__ float g_ns[(size_t)B_SZ * NN * HID];        // node states [B,9,256]  (151 MB)
__device__ float g_Y [(size_t)B_SZ * NN * 2 * HID];    // per-step GEMM out [B,9,512] (302 MB)
__device__ float g_Wc[512 * 256];                      // [U1 ; U2*M]
__device__ float g_c [256];                            // U2*msg_b + upd_b

// ---------------- f32x2 packed-FMA helpers (sm_100+ PTX) -------------------
static __device__ __forceinline__ void ffma2(unsigned long long &d,
                                             unsigned long long a,
                                             unsigned long long b) {
    asm("fma.rn.f32x2 %0, %1, %2, %0;" : "+l"(d) : "l"(a), "l"(b));
}
static __device__ __forceinline__ unsigned long long bcast2(float x) {
    unsigned long long r;
    asm("mov.b64 %0, {%1, %1};" : "=l"(r) : "f"(x));
    return r;
}
static __device__ __forceinline__ float2 unpack2(unsigned long long v) {
    float2 r;
    asm("mov.b64 {%0, %1}, %2;" : "=f"(r.x), "=f"(r.y) : "l"(v));
    return r;
}

// ---------------- setup: Wc = [U1 ; U2*M], c = U2*msg_b + upd_b ------------
// upd_w is [256, 512] row-major (torch Linear [out, in]); U1 = cols 0:256,
// U2 = cols 256:512. msg_w is [256, 256] ([out, in]).
// Z-path weight: W2 = U2 @ msg_w  (so Z = ns @ W2^T).
// Bias fold: A is row-stochastic, so agg(msg_b) = msg_b; c = U2@msg_b + upd_b.
__global__ void setup_kernel(const float* __restrict__ upd_w,
                             const float* __restrict__ msg_w,
                             const float* __restrict__ upd_b,
                             const float* __restrict__ msg_b) {
    int o = blockIdx.x;
    int k = threadIdx.x;  // 256 threads
    if (o < 256) {
        g_Wc[o * 256 + k] = upd_w[o * 512 + k];
    } else if (o < 512) {
        int oo = o - 256;
        float s = 0.f;
        #pragma unroll 8
        for (int t = 0; t < 256; ++t)
            s = fmaf(upd_w[oo * 512 + 256 + t], msg_w[t * 256 + k], s);
        g_Wc[o * 256 + k] = s;
    } else {
        float s = upd_b[k];
        for (int t = 0; t < 256; ++t)
            s = fmaf(upd_w[k * 512 + 256 + t], msg_b[t], s);
        g_c[k] = s;
    }
}

// ---------------- NT SGEMM: C[M,N] = A[M,K] * B[N,K]^T (+ optional bias) ---
// BM=128 BN=64 BK=16, 256 threads, 8x4 per-thread tile, f32x2 inner loop.
// Bias epilogue (first GEMM only):
//   C[b, n] += f2n_b[n] + node_enc_b[n&255] + logits[b*9 + (n>>8)] * node_enc_w[n&255]
template<bool WITH_BIAS>
__global__ __launch_bounds__(256)
void gemm_nt(const float* __restrict__ A, const float* __restrict__ Bw,
             float* __restrict__ C, int M, int N, int K,
             const float* __restrict__ colBias,
             const float* __restrict__ hBias,
             const float* __restrict__ hScale,
             const float* __restrict__ logits) {
    const int BM = 128, BN = 64, BK = 16;
    __shared__ float As[BK][BM];
    __shared__ float Bs[BK][BN];

    const int tid = threadIdx.x;
    const int tx = tid & 15;          // 16 col-groups * 4 cols = 64
    const int ty = tid >> 4;          // 16 row-groups * 8 rows = 128
    const int rowbase = ty * 8;
    const int colbase = tx * 4;

    const float* Ablk = A  + (size_t)blockIdx.y * BM * K;
    const float* Bblk = Bw + (size_t)blockIdx.x * BN * K;

    const int ldrow = tid >> 2;           // 0..63
    const int ldk   = (tid & 3) * 4;      // 0,4,8,12

    unsigned long long acc[4][4];         // [n][m-pair]
    #pragma unroll
    for (int n = 0; n < 4; ++n)
        #pragma unroll
        for (int mp = 0; mp < 4; ++mp) acc[n][mp] = 0ull;

    const int ntiles = K / BK;

    // initial tile load
    float4 a0 = *(const float4*)(Ablk + (size_t)ldrow        * K + ldk);
    float4 a1 = *(const float4*)(Ablk + (size_t)(ldrow + 64) * K + ldk);
    float4 b0 = *(const float4*)(Bblk + (size_t)ldrow        * K + ldk);

    As[ldk+0][ldrow] = a0.x; As[ldk+1][ldrow] = a0.y; As[ldk+2][ldrow] = a0.z; As[ldk+3][ldrow] = a0.w;
    As[ldk+0][ldrow+64] = a1.x; As[ldk+1][ldrow+64] = a1.y; As[ldk+2][ldrow+64] = a1.z; As[ldk+3][ldrow+64] = a1.w;
    Bs[ldk+0][ldrow] = b0.x; Bs[ldk+1][ldrow] = b0.y; Bs[ldk+2][ldrow] = b0.z; Bs[ldk+3][ldrow] = b0.w;
    __syncthreads();

    for (int kt = 0; kt < ntiles; ++kt) {
        float4 na0, na1, nb0;
        const bool more = (kt + 1 < ntiles);
        if (more) {
            const float* Ap = Ablk + (size_t)(kt + 1) * BK;
            const float* Bp = Bblk + (size_t)(kt + 1) * BK;
            na0 = *(const float4*)(Ap + (size_t)ldrow        * K + ldk);
            na1 = *(const float4*)(Ap + (size_t)(ldrow + 64) * K + ldk);
            nb0 = *(const float4*)(Bp + (size_t)ldrow        * K + ldk);
        }

        #pragma unroll
        for (int kk = 0; kk < BK; ++kk) {
            ulonglong2 ap01 = *(const ulonglong2*)&As[kk][rowbase];
            ulonglong2 ap23 = *(const ulonglong2*)&As[kk][rowbase + 4];
            float4 bv = *(const float4*)&Bs[kk][colbase];
            unsigned long long bb;
            bb = bcast2(bv.x);
            ffma2(acc[0][0], ap01.x, bb); ffma2(acc[0][1], ap01.y, bb);
            ffma2(acc[0][2], ap23.x, bb); ffma2(acc[0][3], ap23.y, bb);
            bb = bcast2(bv.y);
            ffma2(acc[1][0], ap01.x, bb); ffma2(acc[1][1], ap01.y, bb);
            ffma2(acc[1][2], ap23.x, bb); ffma2(acc[1][3], ap23.y, bb);
            bb = bcast2(bv.z);
            ffma2(acc[2][0], ap01.x, bb); ffma2(acc[2][1], ap01.y, bb);
            ffma2(acc[2][2], ap23.x, bb); ffma2(acc[2][3], ap23.y, bb);
            bb = bcast2(bv.w);
            ffma2(acc[3][0], ap01.x, bb); ffma2(acc[3][1], ap01.y, bb);
            ffma2(acc[3][2], ap23.x, bb); ffma2(acc[3][3], ap23.y, bb);
        }

        if (more) {
            __syncthreads();
            As[ldk+0][ldrow] = na0.x; As[ldk+1][ldrow] = na0.y; As[ldk+2][ldrow] = na0.z; As[ldk+3][ldrow] = na0.w;
            As[ldk+0][ldrow+64] = na1.x; As[ldk+1][ldrow+64] = na1.y; As[ldk+2][ldrow+64] = na1.z; As[ldk+3][ldrow+64] = na1.w;
            Bs[ldk+0][ldrow] = nb0.x; Bs[ldk+1][ldrow] = nb0.y; Bs[ldk+2][ldrow] = nb0.z; Bs[ldk+3][ldrow] = nb0.w;
            __syncthreads();
        }
    }

    // epilogue
    const int growbase = blockIdx.y * BM + rowbase;
    const int gcolbase = blockIdx.x * BN + colbase;
    #pragma unroll
    for (int mp = 0; mp < 4; ++mp) {
        float lo[4], hi[4];
        #pragma unroll
        for (int n = 0; n < 4; ++n) {
            float2 p = unpack2(acc[n][mp]);
            lo[n] = p.x; hi[n] = p.y;
        }
        int r0 = growbase + 2 * mp;
        int r1 = r0 + 1;
        if (WITH_BIAS) {
            #pragma unroll
            for (int n = 0; n < 4; ++n) {
                int col  = gcolbase + n;
                int h    = col & 255;
                int node = col >> 8;
                float base = colBias[col] + hBias[h];
                lo[n] += base + logits[(size_t)r0 * NN + node] * hScale[h];
                hi[n] += base + logits[(size_t)r1 * NN + node] * hScale[h];
            }
        }
        *(float4*)&C[(size_t)r0 * N + gcolbase] = make_float4(lo[0], lo[1], lo[2], lo[3]);
        *(float4*)&C[(size_t)r1 * N + gcolbase] = make_float4(hi[0], hi[1], hi[2], hi[3]);
    }
}

// ---------------- combine: adjacency mix + tanh (steps 1..3) ---------------
// Y[b,i,0:256]   = ns@U1^T       (Y1)
// Y[b,i,256:512] = ns@(U2 M)^T   (Z)
// ns_new[b,i,h] = tanh(Y1[b,i,h] + sum_j A[i,j] Z[b,j,h] + c[h])
// A rows: i=0: all/9 ; i=1: (0,1)/2 ; i=2..6: (0,i,7,8)/4 ; i=7,8: (all - z1)/8
__global__ void combine_kernel(float* __restrict__ ns, const float* __restrict__ Y) {
    const int b = blockIdx.x;
    const int h = threadIdx.x;  // 256
    const float* Yb = Y + (size_t)b * (NN * 512);
    float z[NN];
    float total = 0.f;
    #pragma unroll
    for (int j = 0; j < NN; ++j) { z[j] = Yb[j * 512 + 256 + h]; total += z[j]; }
    const float cb = g_c[h];
    float* nsb = ns + (size_t)b * (NN * HID);

    nsb[0 * 256 + h] = tanhf(Yb[0 * 512 + h] + total * (1.f / 9.f) + cb);
    nsb[1 * 256 + h] = tanhf(Yb[1 * 512 + h] + (z[0] + z[1]) * 0.5f + cb);
    #pragma unroll
    for (int i = 2; i < 7; ++i)
        nsb[i * 256 + h] = tanhf(Yb[i * 512 + h] + (z[0] + z[i] + z[7] + z[8]) * 0.25f + cb);
    const float s78 = (total - z[1]) * 0.125f;
    nsb[7 * 256 + h] = tanhf(Yb[7 * 512 + h] + s78 + cb);
    nsb[8 * 256 + h] = tanhf(Yb[8 * 512 + h] + s78 + cb);
}

// ---------------- last step: nodes 7/8 combine + output dot ----------------
__global__ void final_kernel(const float* __restrict__ Y,
                             const float* __restrict__ out_w,
                             const float* __restrict__ out_b,
                             float* __restrict__ out) {
    const int b = blockIdx.x;
    const int lane = threadIdx.x & 31;
    const int node = 7 + (threadIdx.x >> 5);  // warp0 -> node7 (chronic), warp1 -> node8
    const float* Yb = Y + (size_t)b * (NN * 512);
    float acc = 0.f;
    #pragma unroll
    for (int hh = 0; hh < 8; ++hh) {
        int h = lane + hh * 32;
        float total = 0.f, z1 = 0.f;
        #pragma unroll
        for (int j = 0; j < NN; ++j) {
            float zj = Yb[j * 512 + 256 + h];
            total += zj;
            if (j == 1) z1 = zj;
        }
        float pre = Yb[node * 512 + h] + (total - z1) * 0.125f + g_c[h];
        acc += tanhf(pre) * out_w[h];
    }
    #pragma unroll
    for (int o = 16; o > 0; o >>= 1) acc += __shfl_down_sync(0xffffffffu, acc, o);
    if (lane == 0) out[(node - 7) * B_SZ + b] = acc + out_b[0];
}

// ---------------- launch ---------------------------------------------------
extern "C" void kernel_launch(void* const* d_in, const int* in_sizes, int n_in,
                              void* d_out, int out_size) {
    const float* conc   = (const float*)d_in[0];   // [B, 2048]
    const float* logits = (const float*)d_in[1];   // [B, 9]
    const float* enc_w  = (const float*)d_in[2];   // [256, 1]
    const float* enc_b  = (const float*)d_in[3];   // [256]
    const float* f2n_w  = (const float*)d_in[4];   // [2304, 2048]
    const float* f2n_b  = (const float*)d_in[5];   // [2304]
    const float* msg_w  = (const float*)d_in[6];   // [256, 256]
    const float* msg_b  = (const float*)d_in[7];   // [256]
    const float* upd_w  = (const float*)d_in[8];   // [256, 512]
    const float* upd_b  = (const float*)d_in[9];   // [256]
    const float* out_w  = (const float*)d_in[10];  // [1, 256]
    const float* out_b  = (const float*)d_in[11];  // [1]
    float* out = (float*)d_out;

    float *ns = nullptr, *Y = nullptr, *Wc = nullptr;
    cudaGetSymbolAddress((void**)&ns, g_ns);
    cudaGetSymbolAddress((void**)&Y,  g_Y);
    cudaGetSymbolAddress((void**)&Wc, g_Wc);

    // fold weights: Wc = [U1 ; U2*M], c = U2*msg_b + upd_b
    setup_kernel<<<513, 256>>>(upd_w, msg_w, upd_b, msg_b);

    // ns = conc @ f2n_w^T + f2n_b + node_enc_b + logits*node_enc_w   [B,9,256]
    gemm_nt<true><<<dim3((NN * HID) / 64, B_SZ / 128), 256>>>(
        conc, f2n_w, ns, B_SZ, NN * HID, FDIM, f2n_b, enc_b, enc_w, logits);

    for (int s = 0; s < 4; ++s) {
        // Y = ns @ Wc^T   : [B*9, 256] x [512, 256]^T -> [B*9, 512]
        gemm_nt<false><<<dim3(512 / 64, (B_SZ * NN) / 128), 256>>>(
            ns, Wc, Y, B_SZ * NN, 512, HID, nullptr, nullptr, nullptr, nullptr);
        if (s < 3)
            combine_kernel<<<B_SZ, 256>>>(ns, Y);
        else
            final_kernel<<<B_SZ, 64>>>(Y, out_w, out_b, out);
    }
}

// round 6
// speedup vs baseline: 2.3112x; 2.3112x over previous
#include <cuda_runtime.h>
#include <cuda_bf16.h>
#include <cstdint>

#define B_SZ 16384
#define FDIM 2048
#define HID  256
#define NN   9
#define BROWS (B_SZ * NN)   /* 147456 */

// ---------------- scratch (static device globals; no allocations) ----------
__device__ __align__(256) __nv_bfloat16 g_Xhi[(size_t)B_SZ * FDIM];        // conc hi (67MB)
__device__ __align__(256) __nv_bfloat16 g_Xlo[(size_t)B_SZ * FDIM];        // conc lo
__device__ __align__(256) __nv_bfloat16 g_nshi[(size_t)BROWS * HID];       // node states hi
__device__ __align__(256) __nv_bfloat16 g_nslo[(size_t)BROWS * HID];       // node states lo
__device__ __align__(256) __nv_bfloat16 g_W1hi[(size_t)(NN * HID) * FDIM]; // f2n_w hi (9.4MB)
__device__ __align__(256) __nv_bfloat16 g_W1lo[(size_t)(NN * HID) * FDIM];
__device__ __align__(256) __nv_bfloat16 g_W2hi[512 * 256];                 // Wc hi
__device__ __align__(256) __nv_bfloat16 g_W2lo[512 * 256];                 // Wc lo
__device__ __align__(256) float g_Y[(size_t)BROWS * 512];                  // step GEMM out (302MB)
__device__ __align__(256) float g_Wc[512 * 256];                           // [U1 ; U2*msg_w]
__device__ float g_c[256];                                                 // U2*msg_b + upd_b

// ---------------- PTX helpers (baseline sm_80/sm_100 features only) --------
static __device__ __forceinline__ uint32_t smem_u32(const void* p) {
    uint32_t a;
    asm("{ .reg .u64 t; cvta.to.shared.u64 t, %1; cvt.u32.u64 %0, t; }" : "=r"(a) : "l"(p));
    return a;
}
static __device__ __forceinline__ void cp16(uint32_t s, const void* g) {
    asm volatile("cp.async.cg.shared.global [%0], [%1], 16;" :: "r"(s), "l"(g));
}
static __device__ __forceinline__ void cp_commit() { asm volatile("cp.async.commit_group;"); }
template<int N> static __device__ __forceinline__ void cp_wait() {
    asm volatile("cp.async.wait_group %0;" :: "n"(N));
}
#define LDMX4(r0, r1, r2, r3, a) \
    asm volatile("ldmatrix.sync.aligned.m8n8.x4.shared.b16 {%0,%1,%2,%3}, [%4];" \
        : "=r"(r0), "=r"(r1), "=r"(r2), "=r"(r3) : "r"(a))
#define MMA(c, a, b) \
    asm volatile("mma.sync.aligned.m16n8k16.row.col.f32.bf16.bf16.f32 " \
        "{%0,%1,%2,%3},{%4,%5,%6,%7},{%8,%9},{%0,%1,%2,%3};" \
        : "+f"((c)[0]), "+f"((c)[1]), "+f"((c)[2]), "+f"((c)[3]) \
        : "r"((a)[0]), "r"((a)[1]), "r"((a)[2]), "r"((a)[3]), "r"((b)[0]), "r"((b)[1]))

static __device__ __forceinline__ uint32_t pack_bf2(__nv_bfloat16 a, __nv_bfloat16 b) {
    return (uint32_t)__bfloat16_as_ushort(a) | ((uint32_t)__bfloat16_as_ushort(b) << 16);
}

// ---------------- setup: Wc = [U1 ; U2*msg_w], c = U2*msg_b + upd_b --------
__global__ void setup_kernel(const float* __restrict__ upd_w,
                             const float* __restrict__ msg_w,
                             const float* __restrict__ upd_b,
                             const float* __restrict__ msg_b) {
    int o = blockIdx.x;
    int k = threadIdx.x;  // 256
    if (o < 256) {
        g_Wc[o * 256 + k] = upd_w[o * 512 + k];
    } else if (o < 512) {
        int oo = o - 256;
        float s = 0.f;
        #pragma unroll 8
        for (int t = 0; t < 256; ++t)
            s = fmaf(upd_w[oo * 512 + 256 + t], msg_w[t * 256 + k], s);
        g_Wc[o * 256 + k] = s;
    } else {
        float s = upd_b[k];
        for (int t = 0; t < 256; ++t)
            s = fmaf(upd_w[k * 512 + 256 + t], msg_b[t], s);
        g_c[k] = s;
    }
}

// ---------------- split fp32 -> (bf16 hi, bf16 lo) -------------------------
__global__ void split_kernel(const float* __restrict__ x, __nv_bfloat16* __restrict__ hi,
                             __nv_bfloat16* __restrict__ lo, int n4) {
    int i = blockIdx.x * blockDim.x + threadIdx.x;
    if (i >= n4) return;
    float4 v = ((const float4*)x)[i];
    __nv_bfloat16 h0 = __float2bfloat16(v.x), h1 = __float2bfloat16(v.y);
    __nv_bfloat16 h2 = __float2bfloat16(v.z), h3 = __float2bfloat16(v.w);
    uint2 ph, pl;
    ph.x = pack_bf2(h0, h1);
    ph.y = pack_bf2(h2, h3);
    pl.x = pack_bf2(__float2bfloat16(v.x - __bfloat162float(h0)),
                    __float2bfloat16(v.y - __bfloat162float(h1)));
    pl.y = pack_bf2(__float2bfloat16(v.z - __bfloat162float(h2)),
                    __float2bfloat16(v.w - __bfloat162float(h3)));
    ((uint2*)hi)[i] = ph;
    ((uint2*)lo)[i] = pl;
}

// ---------------- split-bf16 NT GEMM on mma.sync (sm_80-class PTX) --------
// C[M,N] = (Ahi+Alo)[M,K] * (Bhi+Blo)[N,K]^T   (3 bf16 passes, fp32 regs acc)
// CTA tile 128x128, BK=32, 8 warps of 64x32, ldmatrix + cp.async double buffer.
// EPI=0: fp32 store to Cout(ldc). EPI=1: fused biases, split-bf16 -> nshi/nslo.
#define PITCH   80                    /* bytes per 32-bf16 row (16B pad) */
#define TILE_SM (128 * PITCH)         /* 10240 B */
#define STAGE_SM (4 * TILE_SM)        /* 40960 B: Ahi,Alo,Bhi,Blo */
#define SMEM_DYN (2 * STAGE_SM)       /* 81920 B */

template<int EPI>
__global__ __launch_bounds__(256)
void gemm_mma(const __nv_bfloat16* __restrict__ Ahi, const __nv_bfloat16* __restrict__ Alo,
              const __nv_bfloat16* __restrict__ Bhi, const __nv_bfloat16* __restrict__ Blo,
              int K, float* __restrict__ Cout, int ldc,
              __nv_bfloat16* __restrict__ nshi, __nv_bfloat16* __restrict__ nslo,
              const float* __restrict__ colBias, const float* __restrict__ hBias,
              const float* __restrict__ hScale, const float* __restrict__ logits) {
    extern __shared__ char smem_raw[];
    const uint32_t sbase = smem_u32(smem_raw);
    const int tid = threadIdx.x;
    const int wid = tid >> 5, lane = tid & 31;
    const int m0 = blockIdx.y * 128;
    const int n0 = blockIdx.x * 128;
    const int m_w = (wid & 1) * 64;        // warp row offset in tile
    const int n_w = (wid >> 1) * 32;       // warp col offset in tile

    const __nv_bfloat16* gT[4] = { Ahi + (size_t)m0 * K, Alo + (size_t)m0 * K,
                                   Bhi + (size_t)n0 * K, Blo + (size_t)n0 * K };

    // ldmatrix lane-address components
    const int aRow  = m_w + (lane & 15);             // + mb*16
    const int aColB = (lane >> 4) << 4;              // 0 / 16 bytes (k0/k8)
    const int bRow  = n_w + ((lane >> 4) << 3) + (lane & 7);  // + nb16*16
    const int bColB = ((lane >> 3) & 1) << 4;

    float acc[4][4][4];                              // [mb][n8b][frag]
    #pragma unroll
    for (int a = 0; a < 4; ++a)
        #pragma unroll
        for (int b = 0; b < 4; ++b)
            #pragma unroll
            for (int c = 0; c < 4; ++c) acc[a][b][c] = 0.f;

    const int nchunk = K >> 5;

    auto load_chunk = [&](int kt, int s) {
        uint32_t st = sbase + (uint32_t)s * STAGE_SM;
        int k0 = kt * 32;
        #pragma unroll
        for (int t4 = 0; t4 < 4; ++t4) {
            const __nv_bfloat16* g = gT[t4];
            uint32_t tb = st + t4 * TILE_SM;
            #pragma unroll
            for (int i = 0; i < 2; ++i) {
                int id = tid + i * 256;
                int r = id >> 2, ch = id & 3;
                cp16(tb + (uint32_t)(r * PITCH + ch * 16), g + (size_t)r * K + k0 + ch * 8);
            }
        }
        cp_commit();
    };

    load_chunk(0, 0);
    load_chunk(1, 1);

    for (int kt = 0; kt < nchunk; ++kt) {
        const int s = kt & 1;
        if (kt + 1 < nchunk) cp_wait<1>(); else cp_wait<0>();
        __syncthreads();

        const uint32_t st  = sbase + (uint32_t)s * STAGE_SM;
        const uint32_t tAh = st;
        const uint32_t tAl = st + TILE_SM;
        const uint32_t tBh = st + 2 * TILE_SM;
        const uint32_t tBl = st + 3 * TILE_SM;

        #pragma unroll
        for (int kb = 0; kb < 2; ++kb) {
            const uint32_t aoff = (uint32_t)(kb * 32 + aColB);
            const uint32_t boff = (uint32_t)(kb * 32 + bColB);
            uint32_t ah[4][4], al[4][4], bh[8], bl[8];

            #pragma unroll
            for (int mb = 0; mb < 4; ++mb)
                LDMX4(ah[mb][0], ah[mb][1], ah[mb][2], ah[mb][3],
                      tAh + (uint32_t)((aRow + mb * 16) * PITCH) + aoff);
            LDMX4(bh[0], bh[1], bh[2], bh[3], tBh + (uint32_t)(bRow * PITCH) + boff);
            LDMX4(bh[4], bh[5], bh[6], bh[7], tBh + (uint32_t)((bRow + 16) * PITCH) + boff);

            #pragma unroll
            for (int mb = 0; mb < 4; ++mb)
                #pragma unroll
                for (int nb = 0; nb < 4; ++nb)
                    MMA(acc[mb][nb], ah[mb], &bh[nb * 2]);

            LDMX4(bl[0], bl[1], bl[2], bl[3], tBl + (uint32_t)(bRow * PITCH) + boff);
            LDMX4(bl[4], bl[5], bl[6], bl[7], tBl + (uint32_t)((bRow + 16) * PITCH) + boff);

            #pragma unroll
            for (int mb = 0; mb < 4; ++mb)
                #pragma unroll
                for (int nb = 0; nb < 4; ++nb)
                    MMA(acc[mb][nb], ah[mb], &bl[nb * 2]);

            #pragma unroll
            for (int mb = 0; mb < 4; ++mb)
                LDMX4(al[mb][0], al[mb][1], al[mb][2], al[mb][3],
                      tAl + (uint32_t)((aRow + mb * 16) * PITCH) + aoff);

            #pragma unroll
            for (int mb = 0; mb < 4; ++mb)
                #pragma unroll
                for (int nb = 0; nb < 4; ++nb)
                    MMA(acc[mb][nb], al[mb], &bh[nb * 2]);
        }

        __syncthreads();
        if (kt + 2 < nchunk) load_chunk(kt + 2, s);
    }

    // ---- epilogue ----
    const int g  = lane >> 2;
    const int t2 = (lane & 3) * 2;
    if (EPI == 0) {
        #pragma unroll
        for (int mb = 0; mb < 4; ++mb) {
            const int r0 = m0 + m_w + mb * 16 + g;
            #pragma unroll
            for (int nb = 0; nb < 4; ++nb) {
                const int col = n0 + n_w + nb * 8 + t2;
                float2 v0 = make_float2(acc[mb][nb][0], acc[mb][nb][1]);
                float2 v1 = make_float2(acc[mb][nb][2], acc[mb][nb][3]);
                *(float2*)&Cout[(size_t)r0 * ldc + col] = v0;
                *(float2*)&Cout[(size_t)(r0 + 8) * ldc + col] = v1;
            }
        }
    } else {
        const int node = n0 >> 8;
        #pragma unroll
        for (int mb = 0; mb < 4; ++mb) {
            const int r0 = m0 + m_w + mb * 16 + g;
            const int r1 = r0 + 8;
            const float lg0 = logits[(size_t)r0 * NN + node];
            const float lg1 = logits[(size_t)r1 * NN + node];
            const size_t base0 = ((size_t)r0 * NN + node) * 256;
            const size_t base1 = ((size_t)r1 * NN + node) * 256;
            #pragma unroll
            for (int nb = 0; nb < 4; ++nb) {
                const int col = n0 + n_w + nb * 8 + t2;
                const int h = col & 255;
                const float cb0 = colBias[col] + hBias[h];
                const float cb1 = colBias[col + 1] + hBias[h + 1];
                const float s0 = hScale[h], s1 = hScale[h + 1];
                float v00 = acc[mb][nb][0] + cb0 + lg0 * s0;
                float v01 = acc[mb][nb][1] + cb1 + lg0 * s1;
                float v10 = acc[mb][nb][2] + cb0 + lg1 * s0;
                float v11 = acc[mb][nb][3] + cb1 + lg1 * s1;
                __nv_bfloat16 e00 = __float2bfloat16(v00), e01 = __float2bfloat16(v01);
                __nv_bfloat16 e10 = __float2bfloat16(v10), e11 = __float2bfloat16(v11);
                *(uint32_t*)&nshi[base0 + h] = pack_bf2(e00, e01);
                *(uint32_t*)&nslo[base0 + h] = pack_bf2(__float2bfloat16(v00 - __bfloat162float(e00)),
                                                        __float2bfloat16(v01 - __bfloat162float(e01)));
                *(uint32_t*)&nshi[base1 + h] = pack_bf2(e10, e11);
                *(uint32_t*)&nslo[base1 + h] = pack_bf2(__float2bfloat16(v10 - __bfloat162float(e10)),
                                                        __float2bfloat16(v11 - __bfloat162float(e11)));
            }
        }
    }
}

// ---------------- combine: adjacency mix + tanh -> split bf16 --------------
// Y[b,i,0:256] = ns@U1^T ; Y[b,i,256:512] = ns@(U2*msg_w)^T (=Z)
// new[b,i,h] = tanh(Y1 + sum_j A[i,j] Z[b,j,h] + c[h])
__global__ void combine_kernel(__nv_bfloat16* __restrict__ nshi,
                               __nv_bfloat16* __restrict__ nslo,
                               const float* __restrict__ Y) {
    const int b = blockIdx.x;
    const int h = threadIdx.x;  // 256
    const float* Yb = Y + (size_t)b * (NN * 512);
    float z[NN];
    float total = 0.f;
    #pragma unroll
    for (int j = 0; j < NN; ++j) { z[j] = Yb[j * 512 + 256 + h]; total += z[j]; }
    const float cb = g_c[h];
    const size_t base = (size_t)b * (NN * HID) + h;

    float pre[NN];
    pre[0] = Yb[0 * 512 + h] + total * (1.f / 9.f) + cb;
    pre[1] = Yb[1 * 512 + h] + (z[0] + z[1]) * 0.5f + cb;
    #pragma unroll
    for (int i = 2; i < 7; ++i)
        pre[i] = Yb[i * 512 + h] + (z[0] + z[i] + z[7] + z[8]) * 0.25f + cb;
    const float s78 = (total - z[1]) * 0.125f;
    pre[7] = Yb[7 * 512 + h] + s78 + cb;
    pre[8] = Yb[8 * 512 + h] + s78 + cb;
    #pragma unroll
    for (int i = 0; i < NN; ++i) {
        float t = tanhf(pre[i]);
        __nv_bfloat16 e = __float2bfloat16(t);
        nshi[base + i * 256] = e;
        nslo[base + i * 256] = __float2bfloat16(t - __bfloat162float(e));
    }
}

// ---------------- last step: nodes 7/8 combine + output dot ----------------
__global__ void final_kernel(const float* __restrict__ Y,
                             const float* __restrict__ out_w,
                             const float* __restrict__ out_b,
                             float* __restrict__ out) {
    const int b = blockIdx.x;
    const int lane = threadIdx.x & 31;
    const int node = 7 + (threadIdx.x >> 5);  // warp0 -> node7 (chronic), warp1 -> node8
    const float* Yb = Y + (size_t)b * (NN * 512);
    float acc = 0.f;
    #pragma unroll
    for (int hh = 0; hh < 8; ++hh) {
        int h = lane + hh * 32;
        float total = 0.f, z1 = 0.f;
        #pragma unroll
        for (int j = 0; j < NN; ++j) {
            float zj = Yb[j * 512 + 256 + h];
            total += zj;
            if (j == 1) z1 = zj;
        }
        float pre = Yb[node * 512 + h] + (total - z1) * 0.125f + g_c[h];
        acc += tanhf(pre) * out_w[h];
    }
    #pragma unroll
    for (int o = 16; o > 0; o >>= 1) acc += __shfl_down_sync(0xffffffffu, acc, o);
    if (lane == 0) out[(node - 7) * B_SZ + b] = acc + out_b[0];
}

// ---------------- launch ---------------------------------------------------
extern "C" void kernel_launch(void* const* d_in, const int* in_sizes, int n_in,
                              void* d_out, int out_size) {
    const float* conc   = (const float*)d_in[0];   // [B, 2048]
    const float* logits = (const float*)d_in[1];   // [B, 9]
    const float* enc_w  = (const float*)d_in[2];   // [256, 1]
    const float* enc_b  = (const float*)d_in[3];   // [256]
    const float* f2n_w  = (const float*)d_in[4];   // [2304, 2048]
    const float* f2n_b  = (const float*)d_in[5];   // [2304]
    const float* msg_w  = (const float*)d_in[6];   // [256, 256]
    const float* msg_b  = (const float*)d_in[7];   // [256]
    const float* upd_w  = (const float*)d_in[8];   // [256, 512]
    const float* upd_b  = (const float*)d_in[9];   // [256]
    const float* out_w  = (const float*)d_in[10];  // [1, 256]
    const float* out_b  = (const float*)d_in[11];  // [1]
    float* out = (float*)d_out;

    __nv_bfloat16 *Xhi, *Xlo, *nshi, *nslo, *W1hi, *W1lo, *W2hi, *W2lo;
    float *Y, *Wc;
    cudaGetSymbolAddress((void**)&Xhi,  g_Xhi);
    cudaGetSymbolAddress((void**)&Xlo,  g_Xlo);
    cudaGetSymbolAddress((void**)&nshi, g_nshi);
    cudaGetSymbolAddress((void**)&nslo, g_nslo);
    cudaGetSymbolAddress((void**)&W1hi, g_W1hi);
    cudaGetSymbolAddress((void**)&W1lo, g_W1lo);
    cudaGetSymbolAddress((void**)&W2hi, g_W2hi);
    cudaGetSymbolAddress((void**)&W2lo, g_W2lo);
    cudaGetSymbolAddress((void**)&Y,    g_Y);
    cudaGetSymbolAddress((void**)&Wc,   g_Wc);

    cudaFuncSetAttribute((const void*)gemm_mma<0>, cudaFuncAttributeMaxDynamicSharedMemorySize, SMEM_DYN);
    cudaFuncSetAttribute((const void*)gemm_mma<1>, cudaFuncAttributeMaxDynamicSharedMemorySize, SMEM_DYN);

    // fold weights, then split everything to bf16 hi/lo
    setup_kernel<<<513, 256>>>(upd_w, msg_w, upd_b, msg_b);
    int n4 = (B_SZ * FDIM) / 4;
    split_kernel<<<(n4 + 255) / 256, 256>>>(conc, Xhi, Xlo, n4);
    n4 = (NN * HID * FDIM) / 4;
    split_kernel<<<(n4 + 255) / 256, 256>>>(f2n_w, W1hi, W1lo, n4);
    n4 = (512 * 256) / 4;
    split_kernel<<<(n4 + 255) / 256, 256>>>(Wc, W2hi, W2lo, n4);

    // ns = conc @ f2n_w^T + biases  -> split-bf16 node states [B*9, 256]
    gemm_mma<1><<<dim3((NN * HID) / 128, B_SZ / 128), 256, SMEM_DYN>>>(
        Xhi, Xlo, W1hi, W1lo, FDIM, nullptr, 0,
        nshi, nslo, f2n_b, enc_b, enc_w, logits);

    for (int s = 0; s < 4; ++s) {
        // Y = ns @ Wc^T : [B*9, 256] x [512, 256]^T -> [B*9, 512] fp32
        gemm_mma<0><<<dim3(512 / 128, BROWS / 128), 256, SMEM_DYN>>>(
            nshi, nslo, W2hi, W2lo, HID, Y, 512,
            nullptr, nullptr, nullptr, nullptr, nullptr, nullptr);
        if (s < 3)
            combine_kernel<<<B_SZ, 256>>>(nshi, nslo, Y);
        else
            final_kernel<<<B_SZ, 64>>>(Y, out_w, out_b, out);
    }
}